// round 8
// baseline (speedup 1.0000x reference)
#include <cuda_runtime.h>

// ============================================================================
// Soft K-means — R7 resubmit (prior round failed on infra, not the kernel).
// pA (dot+max+exp) keeps the R3 (c,h) lane layout; e stored to per-warp smem.
// pB (accumulate) is transposed: lane = dim-pair, 1 LDS.64 per query + 4
// broadcast LDS.128 for the e-row; denominator summed in registers (f32x2).
// MIO ops/query: 25 -> 19 (8 LDS + 5 SHFL + 1 STS in pA, 5 LDS in pB).
// ============================================================================

#define NQ        (1 << 21)
#define DIM       64
#define NCLS      16
#define NSUP      512
#define NITER     50
#define BETA_F    5.0f
#define TILE_Q    64
#define NTILES    (NQ / TILE_Q)
#define GRID_MAIN 296
#define TPB       256
#define NWARPS    (TPB / 32)
#define QPW       (TILE_Q / NWARPS)    // 8

__device__ float  g_sup_sum[NCLS][DIM];
__device__ float  g_counts[NCLS];
__device__ float  g_cs[NCLS][DIM];                 // 2*beta*centroid
__device__ float  g_bias[NCLS];                    // beta*|centroid|^2
__device__ float  g_part[GRID_MAIN][NCLS][DIM];    // per-block partials
__device__ float  g_pden[GRID_MAIN][NCLS];
__device__ int    g_match;
__device__ int    g_lab64;

// ---------------- helpers ---------------------------------------------------
__device__ __forceinline__ float2 ffma2(const float2 a, const float2 b,
                                        const float2 c) {
    float2 r;
    asm("{.reg .b64 ra,rb,rc;\n\t"
        "mov.b64 ra,{%2,%3};\n\tmov.b64 rb,{%4,%5};\n\tmov.b64 rc,{%6,%7};\n\t"
        "fma.rn.f32x2 rc, ra, rb, rc;\n\tmov.b64 {%0,%1}, rc;}\n"
        : "=f"(r.x), "=f"(r.y)
        : "f"(a.x), "f"(a.y), "f"(b.x), "f"(b.y), "f"(c.x), "f"(c.y));
    return r;
}
__device__ __forceinline__ float2 fadd2(const float2 a, const float2 b) {
    float2 r;
    asm("{.reg .b64 ra,rb;\n\t"
        "mov.b64 ra,{%2,%3};\n\tmov.b64 rb,{%4,%5};\n\t"
        "add.rn.f32x2 ra, ra, rb;\n\tmov.b64 {%0,%1}, ra;}\n"
        : "=f"(r.x), "=f"(r.y)
        : "f"(a.x), "f"(a.y), "f"(b.x), "f"(b.y));
    return r;
}
__device__ __forceinline__ float frcp(float x) {
    float r;
    asm("rcp.approx.f32 %0, %1;" : "=f"(r) : "f"(x));
    return r;
}
__device__ __forceinline__ void cp16(void* smem_dst, const void* gsrc) {
    unsigned s = (unsigned)__cvta_generic_to_shared(smem_dst);
    asm volatile("cp.async.cg.shared.global [%0], [%1], 16;\n"
                 :: "r"(s), "l"(gsrc));
}
#define CP_COMMIT() asm volatile("cp.async.commit_group;\n" ::: "memory")
#define CP_WAIT1()  asm volatile("cp.async.wait_group 1;\n" ::: "memory")

__device__ __forceinline__ void stage_tile(float* dst, const float* __restrict__ qf,
                                           int tile, int tid) {
    const float4* src = (const float4*)(qf + (size_t)tile * (TILE_Q * DIM));
    float4* d4 = (float4*)dst;
#pragma unroll
    for (int k = 0; k < 4; k++)
        cp16(&d4[k * TPB + tid], &src[k * TPB + tid]);
}

// ---------------- init ------------------------------------------------------
__global__ void init_kernel(const float* __restrict__ sup, const void* slab) {
    __shared__ int s64;
    if (threadIdx.x == 0) {
        const unsigned long long* p = (const unsigned long long*)slab;
        int is64 = 1;
#pragma unroll
        for (int i = 0; i < 4; i++)
            if ((p[i] >> 32) != 0ull) is64 = 0;
        s64 = is64;
        g_lab64 = is64;
        g_match = 0;
    }
    __syncthreads();
    const int is64 = s64;
    const int c = threadIdx.x >> 5;
    const int j = threadIdx.x & 31;
    const long long* l64 = (const long long*)slab;
    const int*       l32 = (const int*)slab;

    float sx = 0.f, sy = 0.f;
    int cnt = 0;
    for (int s = 0; s < NSUP; s++) {
        int lbl = is64 ? (int)l64[s] : l32[s];
        if (lbl == c) {
            float2 v = ((const float2*)(sup + s * DIM))[j];
            sx += v.x; sy += v.y; cnt++;
        }
    }
    g_sup_sum[c][2 * j]     = sx;
    g_sup_sum[c][2 * j + 1] = sy;
    float inv = 1.0f / (float)cnt;
    float c0 = sx * inv, c1 = sy * inv;
    g_cs[c][2 * j]     = 2.0f * BETA_F * c0;
    g_cs[c][2 * j + 1] = 2.0f * BETA_F * c1;
    float sq = c0 * c0 + c1 * c1;
#pragma unroll
    for (int m = 16; m > 0; m >>= 1)
        sq += __shfl_xor_sync(0xffffffffu, sq, m);
    if (j == 0) {
        g_counts[c] = (float)cnt;
        g_bias[c]   = BETA_F * sq;
    }
}

// ---------------- fused iteration kernel ------------------------------------
__global__ void __launch_bounds__(TPB, 2)
iter_kernel(const float* __restrict__ qf) {
    __shared__ alignas(16) float sbuf[2][TILE_Q * DIM];   // 32 KB
    __shared__ alignas(16) float sE[NWARPS][QPW][16];     // 4 KB
    __shared__ float facc[NCLS][DIM];                     // 4 KB
    __shared__ float sws[32];

    const int tid  = threadIdx.x;
    const int wid  = tid >> 5;
    const int lane = tid & 31;
    const int c    = lane & 15;
    const int h    = lane >> 4;

    float4 cs[8];
    const float4* csrow = (const float4*)g_cs[c];
#pragma unroll
    for (int k = 0; k < 8; k++) cs[k] = csrow[2 * k + h];
    const float bias = g_bias[c];

    float2 acc[16];                 // lane = dim-pair: class i, dims 2lane..+1
#pragma unroll
    for (int i = 0; i < 16; i++) { acc[i].x = 0.f; acc[i].y = 0.f; }
    float ws = 0.f;                 // lanes<16: sum of w for class==lane

    int t = blockIdx.x;
    if (t < NTILES) stage_tile(sbuf[0], qf, t, tid);
    CP_COMMIT();
    int buf = 0;

    for (; t < NTILES; t += gridDim.x) {
        int tn = t + gridDim.x;
        if (tn < NTILES) stage_tile(sbuf[buf ^ 1], qf, tn, tid);
        CP_COMMIT();
        CP_WAIT1();
        __syncthreads();

        const float* base = sbuf[buf] + wid * (QPW * DIM);

        // ---- pA: dots -> logits (8-wide ILP) ----
        float logit[QPW];
#pragma unroll
        for (int qi = 0; qi < QPW; qi++) {
            const float4* qrow = (const float4*)(base + qi * DIM);
            float2 dA = {0.f, 0.f}, dB = {0.f, 0.f};
#pragma unroll
            for (int k = 0; k < 8; k++) {
                float4 qv = qrow[2 * k + h];
                float2 q01 = {qv.x, qv.y}, q23 = {qv.z, qv.w};
                float2 c01 = {cs[k].x, cs[k].y}, c23 = {cs[k].z, cs[k].w};
                dA = ffma2(q01, c01, dA);
                dB = ffma2(q23, c23, dB);
            }
            float dot = (dA.x + dA.y) + (dB.x + dB.y);
            dot += __shfl_xor_sync(0xffffffffu, dot, 16);
            logit[qi] = dot - bias;
        }

        // ---- max over classes (butterflies, interleaved) ----
        float mx[QPW];
#pragma unroll
        for (int qi = 0; qi < QPW; qi++) mx[qi] = logit[qi];
#pragma unroll
        for (int msk = 8; msk >= 1; msk >>= 1) {
#pragma unroll
            for (int qi = 0; qi < QPW; qi++)
                mx[qi] = fmaxf(mx[qi], __shfl_xor_sync(0xffffffffu, mx[qi], msk));
        }

        // ---- exp, stash e per class into per-warp smem ----
        float e_reg[QPW];
#pragma unroll
        for (int qi = 0; qi < QPW; qi++)
            e_reg[qi] = __expf(logit[qi] - mx[qi]);
        if (lane < 16) {
#pragma unroll
            for (int qi = 0; qi < QPW; qi++) sE[wid][qi][lane] = e_reg[qi];
        }
        __syncwarp();

        // ---- pB: transposed accumulate (lane = dim-pair) ----
        const float* eb = &sE[wid][0][0];
#pragma unroll 2
        for (int qi = 0; qi < QPW; qi++) {
            float2 q2 = *(const float2*)(base + qi * DIM + 2 * lane);
            const float4* er = (const float4*)(eb + qi * 16);
            float4 r0 = er[0], r1 = er[1], r2 = er[2], r3 = er[3];

            float2 s1 = fadd2({r0.x, r0.y}, {r1.x, r1.y});
            float2 s2 = fadd2({r0.z, r0.w}, {r1.z, r1.w});
            float2 s3 = fadd2({r2.x, r2.y}, {r3.x, r3.y});
            float2 s4 = fadd2({r2.z, r2.w}, {r3.z, r3.w});
            float2 s5 = fadd2(s1, s2);
            float2 s6 = fadd2(s3, s4);
            float2 s7 = fadd2(s5, s6);
            float inv = frcp(s7.x + s7.y);

            float qx = q2.x * inv, qy = q2.y * inv;
            float ev[16] = {r0.x, r0.y, r0.z, r0.w, r1.x, r1.y, r1.z, r1.w,
                            r2.x, r2.y, r2.z, r2.w, r3.x, r3.y, r3.z, r3.w};
#pragma unroll
            for (int i = 0; i < 16; i++) {
                acc[i].x = fmaf(ev[i], qx, acc[i].x);
                acc[i].y = fmaf(ev[i], qy, acc[i].y);
            }
            if (lane < 16) ws = fmaf(e_reg[qi], inv, ws);
        }

        buf ^= 1;
        __syncthreads();
    }

    // ---- deterministic serialized flush into [16][64] partials ----
    for (int r = 0; r < NWARPS; r++) {
        if (wid == r) {
            if (r == 0) {
#pragma unroll
                for (int i = 0; i < 16; i++) {
                    facc[i][2 * lane]     = acc[i].x;
                    facc[i][2 * lane + 1] = acc[i].y;
                }
                sws[lane] = ws;
            } else {
#pragma unroll
                for (int i = 0; i < 16; i++) {
                    facc[i][2 * lane]     += acc[i].x;
                    facc[i][2 * lane + 1] += acc[i].y;
                }
                sws[lane] += ws;
            }
        }
        __syncthreads();
    }
    {
        const float4* fs = (const float4*)&facc[0][0];
        ((float4*)&g_part[blockIdx.x][0][0])[tid] = fs[tid];
        if (tid < NCLS) g_pden[blockIdx.x][tid] = sws[tid];
    }
}

// ---------------- centroid update (16 blocks) -------------------------------
__global__ void reduce_kernel() {
    __shared__ float red[4][DIM];
    __shared__ float dch[4];
    __shared__ float sqv[DIM];
    __shared__ float den_s;

    const int c  = blockIdx.x;
    const int tid = threadIdx.x;          // 256
    const int d  = tid & 63;
    const int ch = tid >> 6;              // 0..3
    const int per = GRID_MAIN / 4;        // 74

    float s = 0.f, ds = 0.f;
    const int b0 = ch * per;
    for (int b = b0; b < b0 + per; b++) {
        s += g_part[b][c][d];
        if (d == 0) ds += g_pden[b][c];
    }
    red[ch][d] = s;
    if (d == 0) dch[ch] = ds;
    __syncthreads();

    if (tid == 0)
        den_s = g_counts[c] + dch[0] + dch[1] + dch[2] + dch[3];
    __syncthreads();

    if (tid < DIM) {
        float tot = red[0][tid] + red[1][tid] + red[2][tid] + red[3][tid];
        float num = g_sup_sum[c][tid] + tot;
        float cd  = num / den_s;
        g_cs[c][tid] = 2.0f * BETA_F * cd;
        sqv[tid] = cd * cd;
    }
    __syncthreads();
    if (tid == 0) {
        float sq = 0.f;
#pragma unroll
        for (int k = 0; k < DIM; k++) sq += sqv[k];
        g_bias[c] = BETA_F * sq;
    }
}

// ---------------- final prediction (unchanged from R3) ----------------------
__global__ void __launch_bounds__(TPB, 2)
predict_kernel(const float* __restrict__ qf, const void* __restrict__ qlab) {
    __shared__ alignas(16) float sbuf[2][TILE_Q * DIM];
    __shared__ int scnt[NWARPS];

    const int tid  = threadIdx.x;
    const int wid  = tid >> 5;
    const int lane = tid & 31;
    const int c    = lane & 15;
    const int h    = lane >> 4;

    float4 cs[8];
    const float4* csrow = (const float4*)g_cs[c];
#pragma unroll
    for (int k = 0; k < 8; k++) cs[k] = csrow[2 * k + h];
    const float bias = g_bias[c];

    const int is64 = g_lab64;
    const long long* L64 = (const long long*)qlab;
    const int*       L32 = (const int*)qlab;

    int cnt = 0;
    int t = blockIdx.x;
    if (t < NTILES) stage_tile(sbuf[0], qf, t, tid);
    CP_COMMIT();
    int buf = 0;

    for (; t < NTILES; t += gridDim.x) {
        int tn = t + gridDim.x;
        if (tn < NTILES) stage_tile(sbuf[buf ^ 1], qf, tn, tid);
        CP_COMMIT();
        CP_WAIT1();
        __syncthreads();

        const float* base = sbuf[buf] + wid * (QPW * DIM);

        float v[QPW];
#pragma unroll
        for (int qi = 0; qi < QPW; qi++) {
            const float4* qrow = (const float4*)(base + qi * DIM);
            float2 dA = {0.f, 0.f}, dB = {0.f, 0.f};
#pragma unroll
            for (int k = 0; k < 8; k++) {
                float4 qv = qrow[2 * k + h];
                float2 q01 = {qv.x, qv.y}, q23 = {qv.z, qv.w};
                float2 c01 = {cs[k].x, cs[k].y}, c23 = {cs[k].z, cs[k].w};
                dA = ffma2(q01, c01, dA);
                dB = ffma2(q23, c23, dB);
            }
            float dot = (dA.x + dA.y) + (dB.x + dB.y);
            dot += __shfl_xor_sync(0xffffffffu, dot, 16);
            v[qi] = dot - bias;
        }

        int bi[QPW];
#pragma unroll
        for (int qi = 0; qi < QPW; qi++) bi[qi] = c;
#pragma unroll
        for (int msk = 8; msk >= 1; msk >>= 1) {
#pragma unroll
            for (int qi = 0; qi < QPW; qi++) {
                float ov = __shfl_xor_sync(0xffffffffu, v[qi], msk);
                int   oi = __shfl_xor_sync(0xffffffffu, bi[qi], msk);
                if (ov > v[qi] || (ov == v[qi] && oi < bi[qi])) {
                    v[qi] = ov; bi[qi] = oi;
                }
            }
        }
        if (lane == 0) {
#pragma unroll
            for (int qi = 0; qi < QPW; qi++) {
                int qg = t * TILE_Q + wid * QPW + qi;
                int lbl = is64 ? (int)L64[qg] : L32[qg];
                if (bi[qi] == lbl) cnt++;
            }
        }
        buf ^= 1;
        __syncthreads();
    }

    if (lane == 0) scnt[wid] = cnt;
    __syncthreads();
    if (tid == 0) {
        int bc = 0;
#pragma unroll
        for (int w = 0; w < NWARPS; w++) bc += scnt[w];
        atomicAdd(&g_match, bc);
    }
}

__global__ void finalize_kernel(float* out) {
    out[0] = (float)g_match / (float)NQ;
}

// ---------------- launch ----------------------------------------------------
extern "C" void kernel_launch(void* const* d_in, const int* in_sizes, int n_in,
                              void* d_out, int out_size) {
    (void)in_sizes; (void)n_in; (void)out_size;
    const float* sup  = (const float*)d_in[0];
    const float* qf   = (const float*)d_in[1];
    const void*  slab = d_in[2];
    const void*  qlab = d_in[3];
    float* out = (float*)d_out;

    init_kernel<<<1, 512>>>(sup, slab);
    for (int it = 0; it < NITER; ++it) {
        iter_kernel<<<GRID_MAIN, TPB>>>(qf);
        reduce_kernel<<<NCLS, 256>>>();
    }
    predict_kernel<<<GRID_MAIN, TPB>>>(qf, qlab);
    finalize_kernel<<<1, 1>>>(out);
}

// round 10
// speedup vs baseline: 1.1303x; 1.1303x over previous
#include <cuda_runtime.h>
#include <cstdint>

// ============================================================================
// Soft K-means — R9: R3 compute (proven, 318.7us/iter) + TMA bulk staging.
// Single variable changed vs R3: tile staging is one cp.async.bulk (16KB)
// issued by tid0 with mbarrier expect_tx/parity completion, instead of 1024
// per-thread cp.async (LDGSTS rt=8 was eating ~40% of the tile cycles).
// ============================================================================

#define NQ        (1 << 21)
#define DIM       64
#define NCLS      16
#define NSUP      512
#define NITER     50
#define BETA_F    5.0f
#define TILE_Q    64
#define NTILES    (NQ / TILE_Q)
#define GRID_MAIN 296
#define TPB       256
#define NWARPS    (TPB / 32)
#define QPW       (TILE_Q / NWARPS)    // 8
#define TQD       (TILE_Q * DIM)       // 4096 floats
#define TBYTES    (TQD * 4)            // 16384 bytes

__device__ float  g_sup_sum[NCLS][DIM];
__device__ float  g_counts[NCLS];
__device__ float  g_cs[NCLS][DIM];                 // 2*beta*centroid
__device__ float  g_bias[NCLS];                    // beta*|centroid|^2
__device__ float2 g_part[GRID_MAIN][32][16];       // per-block partial sums
__device__ float  g_pden[GRID_MAIN][NCLS];
__device__ int    g_match;
__device__ int    g_lab64;

// ---------------- helpers ---------------------------------------------------
__device__ __forceinline__ float2 ffma2(const float2 a, const float2 b,
                                        const float2 c) {
    float2 r;
    asm("{.reg .b64 ra,rb,rc;\n\t"
        "mov.b64 ra,{%2,%3};\n\tmov.b64 rb,{%4,%5};\n\tmov.b64 rc,{%6,%7};\n\t"
        "fma.rn.f32x2 rc, ra, rb, rc;\n\tmov.b64 {%0,%1}, rc;}\n"
        : "=f"(r.x), "=f"(r.y)
        : "f"(a.x), "f"(a.y), "f"(b.x), "f"(b.y), "f"(c.x), "f"(c.y));
    return r;
}
__device__ __forceinline__ uint32_t smem_u32(const void* p) {
    uint32_t a;
    asm("{ .reg .u64 t; cvta.to.shared.u64 t, %1; cvt.u32.u64 %0, t; }"
        : "=r"(a) : "l"(p));
    return a;
}
__device__ __forceinline__ void mbar_init(uint32_t a, uint32_t n) {
    asm volatile("mbarrier.init.shared.b64 [%0], %1;" :: "r"(a), "r"(n)
                 : "memory");
}
__device__ __forceinline__ void mbar_expect(uint32_t a, uint32_t bytes) {
    asm volatile("mbarrier.arrive.expect_tx.shared.b64 _, [%0], %1;"
                 :: "r"(a), "r"(bytes) : "memory");
}
__device__ __forceinline__ void bulk_g2s(uint32_t dst, const void* src,
                                         uint32_t bytes, uint32_t mbar) {
    asm volatile(
        "cp.async.bulk.shared::cluster.global.mbarrier::complete_tx::bytes "
        "[%0], [%1], %2, [%3];"
        :: "r"(dst), "l"(src), "r"(bytes), "r"(mbar) : "memory");
}
__device__ __forceinline__ void mbar_wait(uint32_t a, uint32_t par) {
    uint32_t done;
    asm volatile(
        "{\n\t.reg .pred p;\n\t"
        "mbarrier.try_wait.parity.acquire.cta.shared::cta.b64 p, [%1], %2;\n\t"
        "selp.b32 %0, 1, 0, p;\n\t}"
        : "=r"(done) : "r"(a), "r"(par) : "memory");
    if (!done) {
        asm volatile(
            "{\n\t.reg .pred P1;\n\t"
            "W_%=:\n\t"
            "mbarrier.try_wait.parity.acquire.cta.shared::cta.b64 P1, [%0], %1, 0x989680;\n\t"
            "@P1 bra.uni D_%=;\n\tbra.uni W_%=;\n\tD_%=:\n\t}"
            :: "r"(a), "r"(par) : "memory");
    }
}

// ---------------- init ------------------------------------------------------
__global__ void init_kernel(const float* __restrict__ sup, const void* slab) {
    __shared__ int s64;
    if (threadIdx.x == 0) {
        const unsigned long long* p = (const unsigned long long*)slab;
        int is64 = 1;
#pragma unroll
        for (int i = 0; i < 4; i++)
            if ((p[i] >> 32) != 0ull) is64 = 0;
        s64 = is64;
        g_lab64 = is64;
        g_match = 0;
    }
    __syncthreads();
    const int is64 = s64;
    const int c = threadIdx.x >> 5;
    const int j = threadIdx.x & 31;
    const long long* l64 = (const long long*)slab;
    const int*       l32 = (const int*)slab;

    float sx = 0.f, sy = 0.f;
    int cnt = 0;
    for (int s = 0; s < NSUP; s++) {
        int lbl = is64 ? (int)l64[s] : l32[s];
        if (lbl == c) {
            float2 v = ((const float2*)(sup + s * DIM))[j];
            sx += v.x; sy += v.y; cnt++;
        }
    }
    g_sup_sum[c][2 * j]     = sx;
    g_sup_sum[c][2 * j + 1] = sy;
    float inv = 1.0f / (float)cnt;
    float c0 = sx * inv, c1 = sy * inv;
    g_cs[c][2 * j]     = 2.0f * BETA_F * c0;
    g_cs[c][2 * j + 1] = 2.0f * BETA_F * c1;
    float sq = c0 * c0 + c1 * c1;
#pragma unroll
    for (int m = 16; m > 0; m >>= 1)
        sq += __shfl_xor_sync(0xffffffffu, sq, m);
    if (j == 0) {
        g_counts[c] = (float)cnt;
        g_bias[c]   = BETA_F * sq;
    }
}

// ---------------- fused iteration kernel (R3 compute + TMA staging) ---------
__global__ void __launch_bounds__(TPB, 2)
iter_kernel(const float* __restrict__ qf) {
    __shared__ alignas(128) float sbuf[2][TQD];          // 2 x 16 KB
    __shared__ alignas(8) unsigned long long s_mb[2];
    __shared__ float2 sacc[32][17];
    __shared__ float  sden[32];

    const int tid  = threadIdx.x;
    const int wid  = tid >> 5;
    const int lane = tid & 31;
    const int c    = lane & 15;
    const int h    = lane >> 4;

    const uint32_t mb0 = smem_u32(&s_mb[0]);
    const uint32_t mb1 = smem_u32(&s_mb[1]);
    const uint32_t sb0 = smem_u32(&sbuf[0][0]);
    const uint32_t sb1 = smem_u32(&sbuf[1][0]);

    if (tid == 0) { mbar_init(mb0, 1); mbar_init(mb1, 1); }
    __syncthreads();

    float4 cs[8];
    const float4* csrow = (const float4*)g_cs[c];
#pragma unroll
    for (int k = 0; k < 8; k++) cs[k] = csrow[2 * k + h];
    const float bias = g_bias[c];

    float2 acc[16];
#pragma unroll
    for (int i = 0; i < 16; i++) { acc[i].x = 0.f; acc[i].y = 0.f; }
    float wsum = 0.f;

    int t = blockIdx.x;
    if (tid == 0 && t < NTILES) {
        mbar_expect(mb0, TBYTES);
        bulk_g2s(sb0, qf + (size_t)t * TQD, TBYTES, mb0);
    }
    int buf = 0;
    uint32_t ph0 = 0, ph1 = 0;

    for (; t < NTILES; t += gridDim.x) {
        int tn = t + gridDim.x;
        if (tid == 0 && tn < NTILES) {
            uint32_t mbn = buf ? mb0 : mb1;
            mbar_expect(mbn, TBYTES);
            bulk_g2s(buf ? sb0 : sb1, qf + (size_t)tn * TQD, TBYTES, mbn);
        }
        if (buf == 0) { mbar_wait(mb0, ph0); ph0 ^= 1; }
        else          { mbar_wait(mb1, ph1); ph1 ^= 1; }

        const float* base = sbuf[buf] + wid * (QPW * DIM);

        // ---- phase 1: 8 independent dot products -> logits ----
        float logit[QPW];
#pragma unroll
        for (int qi = 0; qi < QPW; qi++) {
            const float4* qrow = (const float4*)(base + qi * DIM);
            float2 dA = {0.f, 0.f}, dB = {0.f, 0.f};
#pragma unroll
            for (int k = 0; k < 8; k++) {
                float4 qv = qrow[2 * k + h];
                float2 q01 = {qv.x, qv.y}, q23 = {qv.z, qv.w};
                float2 c01 = {cs[k].x, cs[k].y}, c23 = {cs[k].z, cs[k].w};
                dA = ffma2(q01, c01, dA);
                dB = ffma2(q23, c23, dB);
            }
            float dot = (dA.x + dA.y) + (dB.x + dB.y);
            dot += __shfl_xor_sync(0xffffffffu, dot, 16);
            logit[qi] = dot - bias;
        }

        // ---- phase 2: 8 softmaxes, butterflies interleaved 8-wide ----
        float m[QPW];
#pragma unroll
        for (int qi = 0; qi < QPW; qi++) m[qi] = logit[qi];
#pragma unroll
        for (int msk = 8; msk >= 1; msk >>= 1) {
#pragma unroll
            for (int qi = 0; qi < QPW; qi++)
                m[qi] = fmaxf(m[qi], __shfl_xor_sync(0xffffffffu, m[qi], msk));
        }
        float e[QPW], s[QPW];
#pragma unroll
        for (int qi = 0; qi < QPW; qi++) {
            e[qi] = __expf(logit[qi] - m[qi]);
            s[qi] = e[qi];
        }
#pragma unroll
        for (int msk = 8; msk >= 1; msk >>= 1) {
#pragma unroll
            for (int qi = 0; qi < QPW; qi++)
                s[qi] += __shfl_xor_sync(0xffffffffu, s[qi], msk);
        }
        float wv[QPW];
#pragma unroll
        for (int qi = 0; qi < QPW; qi++) {
            wv[qi] = __fdividef(e[qi], s[qi]);
            wsum += wv[qi];
        }

        // ---- phase 3: weighted accumulation (reload q from smem) ----
        __syncwarp();
#pragma unroll
        for (int qi = 0; qi < QPW; qi++) {
            const float4* qrow = (const float4*)(base + qi * DIM);
            float2 wp = {wv[qi], wv[qi]};
#pragma unroll
            for (int k = 0; k < 8; k++) {
                float4 qv = qrow[2 * k + h];
                float2 q01 = {qv.x, qv.y}, q23 = {qv.z, qv.w};
                acc[2 * k]     = ffma2(wp, q01, acc[2 * k]);
                acc[2 * k + 1] = ffma2(wp, q23, acc[2 * k + 1]);
            }
        }

        buf ^= 1;
        __syncthreads();   // all reads of this buffer done before re-issue
    }

    // ---- deterministic serialized flush ----
    for (int ws = 0; ws < NWARPS; ws++) {
        if (wid == ws) {
            if (ws == 0) {
#pragma unroll
                for (int i = 0; i < 16; i++) sacc[lane][i] = acc[i];
                sden[lane] = wsum;
            } else {
#pragma unroll
                for (int i = 0; i < 16; i++) {
                    sacc[lane][i].x += acc[i].x;
                    sacc[lane][i].y += acc[i].y;
                }
                sden[lane] += wsum;
            }
        }
        __syncthreads();
    }
    if (wid == 0) {
#pragma unroll
        for (int i = 0; i < 16; i++)
            g_part[blockIdx.x][lane][i] = sacc[lane][i];
    }
    if (wid == 1 && lane < 16)
        g_pden[blockIdx.x][lane] = sden[lane];
}

// ---------------- centroid update (16 blocks, deterministic) ----------------
__global__ void reduce_kernel() {
    __shared__ float2 red[8][32];
    __shared__ float  dch[8];
    __shared__ float  sqv[32];
    __shared__ float  den_s;

    const int c     = blockIdx.x;
    const int tid   = threadIdx.x;      // 256
    const int s     = tid & 31;
    const int chunk = tid >> 5;
    const int hh    = s >> 4;
    const int ii    = s & 15;
    const int l     = c + 16 * hh;
    const int per   = GRID_MAIN / 8;    // 37

    float2 t2 = {0.f, 0.f};
    float dsum = 0.f;
    const int b0 = chunk * per;
    for (int b = b0; b < b0 + per; b++) {
        float2 v = g_part[b][l][ii];
        t2.x += v.x; t2.y += v.y;
        if (s == 0) dsum += g_pden[b][c];
    }
    red[chunk][s] = t2;
    if (s == 0) dch[chunk] = dsum;
    __syncthreads();

    if (tid == 0) {
        float dtot = g_counts[c];
        for (int k = 0; k < 8; k++) dtot += dch[k];
        den_s = dtot;
    }
    __syncthreads();

    if (tid < 32) {
        float2 tot = red[0][tid];
#pragma unroll
        for (int k = 1; k < 8; k++) {
            tot.x += red[k][tid].x;
            tot.y += red[k][tid].y;
        }
        const int h2 = tid >> 4, i2 = tid & 15;
        const int k2 = i2 >> 1, r2 = i2 & 1;
        const int d0 = 8 * k2 + 4 * h2 + 2 * r2;
        float num0 = g_sup_sum[c][d0]     + tot.x;
        float num1 = g_sup_sum[c][d0 + 1] + tot.y;
        float c0 = num0 / den_s;
        float c1 = num1 / den_s;
        g_cs[c][d0]     = 2.0f * BETA_F * c0;
        g_cs[c][d0 + 1] = 2.0f * BETA_F * c1;
        sqv[tid] = c0 * c0 + c1 * c1;
    }
    __syncthreads();
    if (tid == 0) {
        float sq = 0.f;
        for (int k = 0; k < 32; k++) sq += sqv[k];
        g_bias[c] = BETA_F * sq;
    }
}

// ---------------- final prediction (R3 compute + TMA staging) ---------------
__global__ void __launch_bounds__(TPB, 2)
predict_kernel(const float* __restrict__ qf, const void* __restrict__ qlab) {
    __shared__ alignas(128) float sbuf[2][TQD];
    __shared__ alignas(8) unsigned long long s_mb[2];
    __shared__ int scnt[NWARPS];

    const int tid  = threadIdx.x;
    const int wid  = tid >> 5;
    const int lane = tid & 31;
    const int c    = lane & 15;
    const int h    = lane >> 4;

    const uint32_t mb0 = smem_u32(&s_mb[0]);
    const uint32_t mb1 = smem_u32(&s_mb[1]);
    const uint32_t sb0 = smem_u32(&sbuf[0][0]);
    const uint32_t sb1 = smem_u32(&sbuf[1][0]);

    if (tid == 0) { mbar_init(mb0, 1); mbar_init(mb1, 1); }
    __syncthreads();

    float4 cs[8];
    const float4* csrow = (const float4*)g_cs[c];
#pragma unroll
    for (int k = 0; k < 8; k++) cs[k] = csrow[2 * k + h];
    const float bias = g_bias[c];

    const int is64 = g_lab64;
    const long long* L64 = (const long long*)qlab;
    const int*       L32 = (const int*)qlab;

    int cnt = 0;
    int t = blockIdx.x;
    if (tid == 0 && t < NTILES) {
        mbar_expect(mb0, TBYTES);
        bulk_g2s(sb0, qf + (size_t)t * TQD, TBYTES, mb0);
    }
    int buf = 0;
    uint32_t ph0 = 0, ph1 = 0;

    for (; t < NTILES; t += gridDim.x) {
        int tn = t + gridDim.x;
        if (tid == 0 && tn < NTILES) {
            uint32_t mbn = buf ? mb0 : mb1;
            mbar_expect(mbn, TBYTES);
            bulk_g2s(buf ? sb0 : sb1, qf + (size_t)tn * TQD, TBYTES, mbn);
        }
        if (buf == 0) { mbar_wait(mb0, ph0); ph0 ^= 1; }
        else          { mbar_wait(mb1, ph1); ph1 ^= 1; }

        const float* base = sbuf[buf] + wid * (QPW * DIM);

        float v[QPW];
#pragma unroll
        for (int qi = 0; qi < QPW; qi++) {
            const float4* qrow = (const float4*)(base + qi * DIM);
            float2 dA = {0.f, 0.f}, dB = {0.f, 0.f};
#pragma unroll
            for (int k = 0; k < 8; k++) {
                float4 qv = qrow[2 * k + h];
                float2 q01 = {qv.x, qv.y}, q23 = {qv.z, qv.w};
                float2 c01 = {cs[k].x, cs[k].y}, c23 = {cs[k].z, cs[k].w};
                dA = ffma2(q01, c01, dA);
                dB = ffma2(q23, c23, dB);
            }
            float dot = (dA.x + dA.y) + (dB.x + dB.y);
            dot += __shfl_xor_sync(0xffffffffu, dot, 16);
            v[qi] = dot - bias;
        }

        int bi[QPW];
#pragma unroll
        for (int qi = 0; qi < QPW; qi++) bi[qi] = c;
#pragma unroll
        for (int msk = 8; msk >= 1; msk >>= 1) {
#pragma unroll
            for (int qi = 0; qi < QPW; qi++) {
                float ov = __shfl_xor_sync(0xffffffffu, v[qi], msk);
                int   oi = __shfl_xor_sync(0xffffffffu, bi[qi], msk);
                if (ov > v[qi] || (ov == v[qi] && oi < bi[qi])) {
                    v[qi] = ov; bi[qi] = oi;
                }
            }
        }
        if (lane == 0) {
#pragma unroll
            for (int qi = 0; qi < QPW; qi++) {
                int qg = t * TILE_Q + wid * QPW + qi;
                int lbl = is64 ? (int)L64[qg] : L32[qg];
                if (bi[qi] == lbl) cnt++;
            }
        }
        buf ^= 1;
        __syncthreads();
    }

    if (lane == 0) scnt[wid] = cnt;
    __syncthreads();
    if (tid == 0) {
        int bc = 0;
#pragma unroll
        for (int w = 0; w < NWARPS; w++) bc += scnt[w];
        atomicAdd(&g_match, bc);
    }
}

__global__ void finalize_kernel(float* out) {
    out[0] = (float)g_match / (float)NQ;
}

// ---------------- launch ----------------------------------------------------
extern "C" void kernel_launch(void* const* d_in, const int* in_sizes, int n_in,
                              void* d_out, int out_size) {
    (void)in_sizes; (void)n_in; (void)out_size;
    const float* sup  = (const float*)d_in[0];
    const float* qf   = (const float*)d_in[1];
    const void*  slab = d_in[2];
    const void*  qlab = d_in[3];
    float* out = (float*)d_out;

    init_kernel<<<1, 512>>>(sup, slab);
    for (int it = 0; it < NITER; ++it) {
        iter_kernel<<<GRID_MAIN, TPB>>>(qf);
        reduce_kernel<<<NCLS, 256>>>();
    }
    predict_kernel<<<GRID_MAIN, TPB>>>(qf, qlab);
    finalize_kernel<<<1, 1>>>(out);
}

// round 14
// speedup vs baseline: 1.1530x; 1.0201x over previous
#include <cuda_runtime.h>
#include <cstdint>

// ============================================================================
// Soft K-means — R11: R9 (TMA staging, best 313us/iter) + MIO-reduced pB that
// KEEPS FFMA2 packing (R7's regression was scalar FMA + latency chains).
// pA: (c,h) lanes, 8 LDS + 5 SHFL + 1 STS/query. pB: lane = dim-pair,
// 1 LDS.64 + 4 broadcast LDS.128, denom = f32x2 register tree + rcp,
// 16 FFMA2/query. Wavefronts/query 25 -> 20.
// ============================================================================

#define NQ        (1 << 21)
#define DIM       64
#define NCLS      16
#define NSUP      512
#define NITER     50
#define BETA_F    5.0f
#define TILE_Q    64
#define NTILES    (NQ / TILE_Q)
#define GRID_MAIN 296
#define TPB       256
#define NWARPS    (TPB / 32)
#define QPW       (TILE_Q / NWARPS)    // 8
#define TQD       (TILE_Q * DIM)       // 4096 floats
#define TBYTES    (TQD * 4)            // 16384 bytes

__device__ float  g_sup_sum[NCLS][DIM];
__device__ float  g_counts[NCLS];
__device__ float  g_cs[NCLS][DIM];                 // 2*beta*centroid
__device__ float  g_bias[NCLS];                    // beta*|centroid|^2
__device__ float  g_part[GRID_MAIN][NCLS][DIM];    // per-block partials
__device__ float  g_pden[GRID_MAIN][NCLS];
__device__ int    g_match;
__device__ int    g_lab64;

// ---------------- helpers ---------------------------------------------------
__device__ __forceinline__ float2 ffma2(const float2 a, const float2 b,
                                        const float2 c) {
    float2 r;
    asm("{.reg .b64 ra,rb,rc;\n\t"
        "mov.b64 ra,{%2,%3};\n\tmov.b64 rb,{%4,%5};\n\tmov.b64 rc,{%6,%7};\n\t"
        "fma.rn.f32x2 rc, ra, rb, rc;\n\tmov.b64 {%0,%1}, rc;}\n"
        : "=f"(r.x), "=f"(r.y)
        : "f"(a.x), "f"(a.y), "f"(b.x), "f"(b.y), "f"(c.x), "f"(c.y));
    return r;
}
__device__ __forceinline__ float2 fadd2(const float2 a, const float2 b) {
    float2 r;
    asm("{.reg .b64 ra,rb;\n\t"
        "mov.b64 ra,{%2,%3};\n\tmov.b64 rb,{%4,%5};\n\t"
        "add.rn.f32x2 ra, ra, rb;\n\tmov.b64 {%0,%1}, ra;}\n"
        : "=f"(r.x), "=f"(r.y)
        : "f"(a.x), "f"(a.y), "f"(b.x), "f"(b.y));
    return r;
}
__device__ __forceinline__ float frcp(float x) {
    float r;
    asm("rcp.approx.f32 %0, %1;" : "=f"(r) : "f"(x));
    return r;
}
__device__ __forceinline__ uint32_t smem_u32(const void* p) {
    uint32_t a;
    asm("{ .reg .u64 t; cvta.to.shared.u64 t, %1; cvt.u32.u64 %0, t; }"
        : "=r"(a) : "l"(p));
    return a;
}
__device__ __forceinline__ void mbar_init(uint32_t a, uint32_t n) {
    asm volatile("mbarrier.init.shared.b64 [%0], %1;" :: "r"(a), "r"(n)
                 : "memory");
}
__device__ __forceinline__ void mbar_expect(uint32_t a, uint32_t bytes) {
    asm volatile("mbarrier.arrive.expect_tx.shared.b64 _, [%0], %1;"
                 :: "r"(a), "r"(bytes) : "memory");
}
__device__ __forceinline__ void bulk_g2s(uint32_t dst, const void* src,
                                         uint32_t bytes, uint32_t mbar) {
    asm volatile(
        "cp.async.bulk.shared::cluster.global.mbarrier::complete_tx::bytes "
        "[%0], [%1], %2, [%3];"
        :: "r"(dst), "l"(src), "r"(bytes), "r"(mbar) : "memory");
}
__device__ __forceinline__ void mbar_wait(uint32_t a, uint32_t par) {
    uint32_t done;
    asm volatile(
        "{\n\t.reg .pred p;\n\t"
        "mbarrier.try_wait.parity.acquire.cta.shared::cta.b64 p, [%1], %2;\n\t"
        "selp.b32 %0, 1, 0, p;\n\t}"
        : "=r"(done) : "r"(a), "r"(par) : "memory");
    if (!done) {
        asm volatile(
            "{\n\t.reg .pred P1;\n\t"
            "W_%=:\n\t"
            "mbarrier.try_wait.parity.acquire.cta.shared::cta.b64 P1, [%0], %1, 0x989680;\n\t"
            "@P1 bra.uni D_%=;\n\tbra.uni W_%=;\n\tD_%=:\n\t}"
            :: "r"(a), "r"(par) : "memory");
    }
}

// ---------------- init ------------------------------------------------------
__global__ void init_kernel(const float* __restrict__ sup, const void* slab) {
    __shared__ int s64;
    if (threadIdx.x == 0) {
        const unsigned long long* p = (const unsigned long long*)slab;
        int is64 = 1;
#pragma unroll
        for (int i = 0; i < 4; i++)
            if ((p[i] >> 32) != 0ull) is64 = 0;
        s64 = is64;
        g_lab64 = is64;
        g_match = 0;
    }
    __syncthreads();
    const int is64 = s64;
    const int c = threadIdx.x >> 5;
    const int j = threadIdx.x & 31;
    const long long* l64 = (const long long*)slab;
    const int*       l32 = (const int*)slab;

    float sx = 0.f, sy = 0.f;
    int cnt = 0;
    for (int s = 0; s < NSUP; s++) {
        int lbl = is64 ? (int)l64[s] : l32[s];
        if (lbl == c) {
            float2 v = ((const float2*)(sup + s * DIM))[j];
            sx += v.x; sy += v.y; cnt++;
        }
    }
    g_sup_sum[c][2 * j]     = sx;
    g_sup_sum[c][2 * j + 1] = sy;
    float inv = 1.0f / (float)cnt;
    float c0 = sx * inv, c1 = sy * inv;
    g_cs[c][2 * j]     = 2.0f * BETA_F * c0;
    g_cs[c][2 * j + 1] = 2.0f * BETA_F * c1;
    float sq = c0 * c0 + c1 * c1;
#pragma unroll
    for (int m = 16; m > 0; m >>= 1)
        sq += __shfl_xor_sync(0xffffffffu, sq, m);
    if (j == 0) {
        g_counts[c] = (float)cnt;
        g_bias[c]   = BETA_F * sq;
    }
}

// ---------------- fused iteration kernel ------------------------------------
__global__ void __launch_bounds__(TPB, 2)
iter_kernel(const float* __restrict__ qf) {
    __shared__ alignas(128) float sbuf[2][TQD];          // 2 x 16 KB
    __shared__ alignas(16) float sE[NWARPS][QPW][16];    // 4 KB
    __shared__ alignas(8) unsigned long long s_mb[2];
    __shared__ float facc[NCLS][DIM];                    // 4 KB
    __shared__ float sws[32];

    const int tid  = threadIdx.x;
    const int wid  = tid >> 5;
    const int lane = tid & 31;
    const int c    = lane & 15;
    const int h    = lane >> 4;

    const uint32_t mb0 = smem_u32(&s_mb[0]);
    const uint32_t mb1 = smem_u32(&s_mb[1]);
    const uint32_t sb0 = smem_u32(&sbuf[0][0]);
    const uint32_t sb1 = smem_u32(&sbuf[1][0]);

    if (tid == 0) { mbar_init(mb0, 1); mbar_init(mb1, 1); }
    __syncthreads();

    float4 cs[8];
    const float4* csrow = (const float4*)g_cs[c];
#pragma unroll
    for (int k = 0; k < 8; k++) cs[k] = csrow[2 * k + h];
    const float bias = g_bias[c];

    float2 acc[16];                 // lane = dim-pair: class i, dims 2lane..+1
#pragma unroll
    for (int i = 0; i < 16; i++) { acc[i].x = 0.f; acc[i].y = 0.f; }
    float ws = 0.f;                 // lanes<16: sum of w for class==lane

    int t = blockIdx.x;
    if (tid == 0 && t < NTILES) {
        mbar_expect(mb0, TBYTES);
        bulk_g2s(sb0, qf + (size_t)t * TQD, TBYTES, mb0);
    }
    int buf = 0;
    uint32_t ph0 = 0, ph1 = 0;

    for (; t < NTILES; t += gridDim.x) {
        int tn = t + gridDim.x;
        if (tid == 0 && tn < NTILES) {
            uint32_t mbn = buf ? mb0 : mb1;
            mbar_expect(mbn, TBYTES);
            bulk_g2s(buf ? sb0 : sb1, qf + (size_t)tn * TQD, TBYTES, mbn);
        }
        if (buf == 0) { mbar_wait(mb0, ph0); ph0 ^= 1; }
        else          { mbar_wait(mb1, ph1); ph1 ^= 1; }

        const float* base = sbuf[buf] + wid * (QPW * DIM);

        // ---- pA: 8 dots -> logits (8-wide ILP) ----
        float logit[QPW];
#pragma unroll
        for (int qi = 0; qi < QPW; qi++) {
            const float4* qrow = (const float4*)(base + qi * DIM);
            float2 dA = {0.f, 0.f}, dB = {0.f, 0.f};
#pragma unroll
            for (int k = 0; k < 8; k++) {
                float4 qv = qrow[2 * k + h];
                float2 q01 = {qv.x, qv.y}, q23 = {qv.z, qv.w};
                float2 c01 = {cs[k].x, cs[k].y}, c23 = {cs[k].z, cs[k].w};
                dA = ffma2(q01, c01, dA);
                dB = ffma2(q23, c23, dB);
            }
            float dot = (dA.x + dA.y) + (dB.x + dB.y);
            dot += __shfl_xor_sync(0xffffffffu, dot, 16);
            logit[qi] = dot - bias;
        }

        // ---- max over classes (interleaved butterflies) ----
        float mx[QPW];
#pragma unroll
        for (int qi = 0; qi < QPW; qi++) mx[qi] = logit[qi];
#pragma unroll
        for (int msk = 8; msk >= 1; msk >>= 1) {
#pragma unroll
            for (int qi = 0; qi < QPW; qi++)
                mx[qi] = fmaxf(mx[qi], __shfl_xor_sync(0xffffffffu, mx[qi], msk));
        }

        // ---- exp, stash e per class into per-warp smem ----
        float e_reg[QPW];
#pragma unroll
        for (int qi = 0; qi < QPW; qi++)
            e_reg[qi] = __expf(logit[qi] - mx[qi]);
        if (lane < 16) {
#pragma unroll
            for (int qi = 0; qi < QPW; qi++) sE[wid][qi][lane] = e_reg[qi];
        }
        __syncwarp();

        // ---- pB: transposed accumulate, FFMA2-packed ----
        const float* eb = &sE[wid][0][0];
#pragma unroll 4
        for (int qi = 0; qi < QPW; qi++) {
            float2 q2 = *(const float2*)(base + qi * DIM + 2 * lane);
            const float4* er = (const float4*)(eb + qi * 16);
            float4 r0 = er[0], r1 = er[1], r2 = er[2], r3 = er[3];

            float2 s1 = fadd2({r0.x, r0.y}, {r1.x, r1.y});
            float2 s2 = fadd2({r0.z, r0.w}, {r1.z, r1.w});
            float2 s3 = fadd2({r2.x, r2.y}, {r3.x, r3.y});
            float2 s4 = fadd2({r2.z, r2.w}, {r3.z, r3.w});
            float2 s5 = fadd2(s1, s2);
            float2 s6 = fadd2(s3, s4);
            float2 s7 = fadd2(s5, s6);
            float inv = frcp(s7.x + s7.y);

            float2 qs = {q2.x * inv, q2.y * inv};
            float ev[16] = {r0.x, r0.y, r0.z, r0.w, r1.x, r1.y, r1.z, r1.w,
                            r2.x, r2.y, r2.z, r2.w, r3.x, r3.y, r3.z, r3.w};
#pragma unroll
            for (int i = 0; i < 16; i++)
                acc[i] = ffma2({ev[i], ev[i]}, qs, acc[i]);
            if (lane < 16) ws = fmaf(e_reg[qi], inv, ws);
        }

        buf ^= 1;
        __syncthreads();   // all reads of this buffer done before re-issue
    }

    // ---- deterministic serialized flush into [16][64] partials ----
    for (int r = 0; r < NWARPS; r++) {
        if (wid == r) {
            if (r == 0) {
#pragma unroll
                for (int i = 0; i < 16; i++) {
                    facc[i][2 * lane]     = acc[i].x;
                    facc[i][2 * lane + 1] = acc[i].y;
                }
                sws[lane] = ws;
            } else {
#pragma unroll
                for (int i = 0; i < 16; i++) {
                    facc[i][2 * lane]     += acc[i].x;
                    facc[i][2 * lane + 1] += acc[i].y;
                }
                sws[lane] += ws;
            }
        }
        __syncthreads();
    }
    {
        const float4* fs = (const float4*)&facc[0][0];
        ((float4*)&g_part[blockIdx.x][0][0])[tid] = fs[tid];
        if (tid < NCLS) g_pden[blockIdx.x][tid] = sws[tid];
    }
}

// ---------------- centroid update (16 blocks) -------------------------------
__global__ void reduce_kernel() {
    __shared__ float red[4][DIM];
    __shared__ float dch[4];
    __shared__ float sqv[DIM];
    __shared__ float den_s;

    const int c  = blockIdx.x;
    const int tid = threadIdx.x;          // 256
    const int d  = tid & 63;
    const int ch = tid >> 6;              // 0..3
    const int per = GRID_MAIN / 4;        // 74

    float s = 0.f, ds = 0.f;
    const int b0 = ch * per;
    for (int b = b0; b < b0 + per; b++) {
        s += g_part[b][c][d];
        if (d == 0) ds += g_pden[b][c];
    }
    red[ch][d] = s;
    if (d == 0) dch[ch] = ds;
    __syncthreads();

    if (tid == 0)
        den_s = g_counts[c] + dch[0] + dch[1] + dch[2] + dch[3];
    __syncthreads();

    if (tid < DIM) {
        float tot = red[0][tid] + red[1][tid] + red[2][tid] + red[3][tid];
        float num = g_sup_sum[c][tid] + tot;
        float cd  = num / den_s;
        g_cs[c][tid] = 2.0f * BETA_F * cd;
        sqv[tid] = cd * cd;
    }
    __syncthreads();
    if (tid == 0) {
        float sq = 0.f;
#pragma unroll
        for (int k = 0; k < DIM; k++) sq += sqv[k];
        g_bias[c] = BETA_F * sq;
    }
}

// ---------------- final prediction (R9, unchanged) --------------------------
__global__ void __launch_bounds__(TPB, 2)
predict_kernel(const float* __restrict__ qf, const void* __restrict__ qlab) {
    __shared__ alignas(128) float sbuf[2][TQD];
    __shared__ alignas(8) unsigned long long s_mb[2];
    __shared__ int scnt[NWARPS];

    const int tid  = threadIdx.x;
    const int wid  = tid >> 5;
    const int lane = tid & 31;
    const int c    = lane & 15;
    const int h    = lane >> 4;

    const uint32_t mb0 = smem_u32(&s_mb[0]);
    const uint32_t mb1 = smem_u32(&s_mb[1]);
    const uint32_t sb0 = smem_u32(&sbuf[0][0]);
    const uint32_t sb1 = smem_u32(&sbuf[1][0]);

    if (tid == 0) { mbar_init(mb0, 1); mbar_init(mb1, 1); }
    __syncthreads();

    float4 cs[8];
    const float4* csrow = (const float4*)g_cs[c];
#pragma unroll
    for (int k = 0; k < 8; k++) cs[k] = csrow[2 * k + h];
    const float bias = g_bias[c];

    const int is64 = g_lab64;
    const long long* L64 = (const long long*)qlab;
    const int*       L32 = (const int*)qlab;

    int cnt = 0;
    int t = blockIdx.x;
    if (tid == 0 && t < NTILES) {
        mbar_expect(mb0, TBYTES);
        bulk_g2s(sb0, qf + (size_t)t * TQD, TBYTES, mb0);
    }
    int buf = 0;
    uint32_t ph0 = 0, ph1 = 0;

    for (; t < NTILES; t += gridDim.x) {
        int tn = t + gridDim.x;
        if (tid == 0 && tn < NTILES) {
            uint32_t mbn = buf ? mb0 : mb1;
            mbar_expect(mbn, TBYTES);
            bulk_g2s(buf ? sb0 : sb1, qf + (size_t)tn * TQD, TBYTES, mbn);
        }
        if (buf == 0) { mbar_wait(mb0, ph0); ph0 ^= 1; }
        else          { mbar_wait(mb1, ph1); ph1 ^= 1; }

        const float* base = sbuf[buf] + wid * (QPW * DIM);

        float v[QPW];
#pragma unroll
        for (int qi = 0; qi < QPW; qi++) {
            const float4* qrow = (const float4*)(base + qi * DIM);
            float2 dA = {0.f, 0.f}, dB = {0.f, 0.f};
#pragma unroll
            for (int k = 0; k < 8; k++) {
                float4 qv = qrow[2 * k + h];
                float2 q01 = {qv.x, qv.y}, q23 = {qv.z, qv.w};
                float2 c01 = {cs[k].x, cs[k].y}, c23 = {cs[k].z, cs[k].w};
                dA = ffma2(q01, c01, dA);
                dB = ffma2(q23, c23, dB);
            }
            float dot = (dA.x + dA.y) + (dB.x + dB.y);
            dot += __shfl_xor_sync(0xffffffffu, dot, 16);
            v[qi] = dot - bias;
        }

        int bi[QPW];
#pragma unroll
        for (int qi = 0; qi < QPW; qi++) bi[qi] = c;
#pragma unroll
        for (int msk = 8; msk >= 1; msk >>= 1) {
#pragma unroll
            for (int qi = 0; qi < QPW; qi++) {
                float ov = __shfl_xor_sync(0xffffffffu, v[qi], msk);
                int   oi = __shfl_xor_sync(0xffffffffu, bi[qi], msk);
                if (ov > v[qi] || (ov == v[qi] && oi < bi[qi])) {
                    v[qi] = ov; bi[qi] = oi;
                }
            }
        }
        if (lane == 0) {
#pragma unroll
            for (int qi = 0; qi < QPW; qi++) {
                int qg = t * TILE_Q + wid * QPW + qi;
                int lbl = is64 ? (int)L64[qg] : L32[qg];
                if (bi[qi] == lbl) cnt++;
            }
        }
        buf ^= 1;
        __syncthreads();
    }

    if (lane == 0) scnt[wid] = cnt;
    __syncthreads();
    if (tid == 0) {
        int bc = 0;
#pragma unroll
        for (int w = 0; w < NWARPS; w++) bc += scnt[w];
        atomicAdd(&g_match, bc);
    }
}

__global__ void finalize_kernel(float* out) {
    out[0] = (float)g_match / (float)NQ;
}

// ---------------- launch ----------------------------------------------------
extern "C" void kernel_launch(void* const* d_in, const int* in_sizes, int n_in,
                              void* d_out, int out_size) {
    (void)in_sizes; (void)n_in; (void)out_size;
    const float* sup  = (const float*)d_in[0];
    const float* qf   = (const float*)d_in[1];
    const void*  slab = d_in[2];
    const void*  qlab = d_in[3];
    float* out = (float*)d_out;

    init_kernel<<<1, 512>>>(sup, slab);
    for (int it = 0; it < NITER; ++it) {
        iter_kernel<<<GRID_MAIN, TPB>>>(qf);
        reduce_kernel<<<NCLS, 256>>>();
    }
    predict_kernel<<<GRID_MAIN, TPB>>>(qf, qlab);
    finalize_kernel<<<1, 1>>>(out);
}

// round 15
// speedup vs baseline: 1.2190x; 1.0572x over previous
#include <cuda_runtime.h>
#include <cstdint>

// ============================================================================
// Soft K-means — R15: R11 compute (proven) restructured into per-warp
// independent tile streams. Each warp owns 8-query (2KB) mini-tiles with its
// own double buffer + mbarrier pair; no __syncthreads in the main loop, so
// warps drift out of phase and fill each other's issue holes.
// ============================================================================

#define NQ        (1 << 21)
#define DIM       64
#define NCLS      16
#define NSUP      512
#define NITER     50
#define BETA_F    5.0f
#define GRID_MAIN 296
#define TPB       256
#define NWARPS    (TPB / 32)
#define QPW       8                     // queries per warp-tile
#define WTD       (QPW * DIM)           // 512 floats = 2KB
#define WBYTES    (WTD * 4)
#define NMT       (NQ / QPW)            // 262144 mini-tiles
#define MSTRIDE   (GRID_MAIN * NWARPS)  // 2368 warp streams
// predict kernel geometry (block tiles, unchanged from R9/R11)
#define TILE_Q    64
#define NTILES    (NQ / TILE_Q)
#define TQD       (TILE_Q * DIM)
#define TBYTES    (TQD * 4)

__device__ float  g_sup_sum[NCLS][DIM];
__device__ float  g_counts[NCLS];
__device__ float  g_cs[NCLS][DIM];                 // 2*beta*centroid
__device__ float  g_bias[NCLS];                    // beta*|centroid|^2
__device__ float  g_part[GRID_MAIN][NCLS][DIM];    // per-block partials
__device__ float  g_pden[GRID_MAIN][NCLS];
__device__ int    g_match;
__device__ int    g_lab64;

// ---------------- helpers ---------------------------------------------------
__device__ __forceinline__ float2 ffma2(const float2 a, const float2 b,
                                        const float2 c) {
    float2 r;
    asm("{.reg .b64 ra,rb,rc;\n\t"
        "mov.b64 ra,{%2,%3};\n\tmov.b64 rb,{%4,%5};\n\tmov.b64 rc,{%6,%7};\n\t"
        "fma.rn.f32x2 rc, ra, rb, rc;\n\tmov.b64 {%0,%1}, rc;}\n"
        : "=f"(r.x), "=f"(r.y)
        : "f"(a.x), "f"(a.y), "f"(b.x), "f"(b.y), "f"(c.x), "f"(c.y));
    return r;
}
__device__ __forceinline__ float2 fadd2(const float2 a, const float2 b) {
    float2 r;
    asm("{.reg .b64 ra,rb;\n\t"
        "mov.b64 ra,{%2,%3};\n\tmov.b64 rb,{%4,%5};\n\t"
        "add.rn.f32x2 ra, ra, rb;\n\tmov.b64 {%0,%1}, ra;}\n"
        : "=f"(r.x), "=f"(r.y)
        : "f"(a.x), "f"(a.y), "f"(b.x), "f"(b.y));
    return r;
}
__device__ __forceinline__ float frcp(float x) {
    float r;
    asm("rcp.approx.f32 %0, %1;" : "=f"(r) : "f"(x));
    return r;
}
__device__ __forceinline__ uint32_t smem_u32(const void* p) {
    uint32_t a;
    asm("{ .reg .u64 t; cvta.to.shared.u64 t, %1; cvt.u32.u64 %0, t; }"
        : "=r"(a) : "l"(p));
    return a;
}
__device__ __forceinline__ void mbar_init(uint32_t a, uint32_t n) {
    asm volatile("mbarrier.init.shared.b64 [%0], %1;" :: "r"(a), "r"(n)
                 : "memory");
}
__device__ __forceinline__ void mbar_expect(uint32_t a, uint32_t bytes) {
    asm volatile("mbarrier.arrive.expect_tx.shared.b64 _, [%0], %1;"
                 :: "r"(a), "r"(bytes) : "memory");
}
__device__ __forceinline__ void bulk_g2s(uint32_t dst, const void* src,
                                         uint32_t bytes, uint32_t mbar) {
    asm volatile(
        "cp.async.bulk.shared::cluster.global.mbarrier::complete_tx::bytes "
        "[%0], [%1], %2, [%3];"
        :: "r"(dst), "l"(src), "r"(bytes), "r"(mbar) : "memory");
}
__device__ __forceinline__ void mbar_wait(uint32_t a, uint32_t par) {
    uint32_t done;
    asm volatile(
        "{\n\t.reg .pred p;\n\t"
        "mbarrier.try_wait.parity.acquire.cta.shared::cta.b64 p, [%1], %2;\n\t"
        "selp.b32 %0, 1, 0, p;\n\t}"
        : "=r"(done) : "r"(a), "r"(par) : "memory");
    if (!done) {
        asm volatile(
            "{\n\t.reg .pred P1;\n\t"
            "W_%=:\n\t"
            "mbarrier.try_wait.parity.acquire.cta.shared::cta.b64 P1, [%0], %1, 0x989680;\n\t"
            "@P1 bra.uni D_%=;\n\tbra.uni W_%=;\n\tD_%=:\n\t}"
            :: "r"(a), "r"(par) : "memory");
    }
}

// ---------------- init ------------------------------------------------------
__global__ void init_kernel(const float* __restrict__ sup, const void* slab) {
    __shared__ int s64;
    if (threadIdx.x == 0) {
        const unsigned long long* p = (const unsigned long long*)slab;
        int is64 = 1;
#pragma unroll
        for (int i = 0; i < 4; i++)
            if ((p[i] >> 32) != 0ull) is64 = 0;
        s64 = is64;
        g_lab64 = is64;
        g_match = 0;
    }
    __syncthreads();
    const int is64 = s64;
    const int c = threadIdx.x >> 5;
    const int j = threadIdx.x & 31;
    const long long* l64 = (const long long*)slab;
    const int*       l32 = (const int*)slab;

    float sx = 0.f, sy = 0.f;
    int cnt = 0;
    for (int s = 0; s < NSUP; s++) {
        int lbl = is64 ? (int)l64[s] : l32[s];
        if (lbl == c) {
            float2 v = ((const float2*)(sup + s * DIM))[j];
            sx += v.x; sy += v.y; cnt++;
        }
    }
    g_sup_sum[c][2 * j]     = sx;
    g_sup_sum[c][2 * j + 1] = sy;
    float inv = 1.0f / (float)cnt;
    float c0 = sx * inv, c1 = sy * inv;
    g_cs[c][2 * j]     = 2.0f * BETA_F * c0;
    g_cs[c][2 * j + 1] = 2.0f * BETA_F * c1;
    float sq = c0 * c0 + c1 * c1;
#pragma unroll
    for (int m = 16; m > 0; m >>= 1)
        sq += __shfl_xor_sync(0xffffffffu, sq, m);
    if (j == 0) {
        g_counts[c] = (float)cnt;
        g_bias[c]   = BETA_F * sq;
    }
}

// ---------------- fused iteration kernel (per-warp streams) -----------------
__global__ void __launch_bounds__(TPB, 2)
iter_kernel(const float* __restrict__ qf) {
    __shared__ alignas(128) float sbuf[NWARPS][2][WTD];  // 32 KB
    __shared__ alignas(16) float sE[NWARPS][QPW][16];    // 4 KB
    __shared__ alignas(8) unsigned long long s_mb[NWARPS][2];
    __shared__ float facc[NCLS][DIM];                    // 4 KB
    __shared__ float sws[32];

    const int tid  = threadIdx.x;
    const int wid  = tid >> 5;
    const int lane = tid & 31;
    const int c    = lane & 15;
    const int h    = lane >> 4;

    const uint32_t mbA = smem_u32(&s_mb[wid][0]);
    const uint32_t mbB = smem_u32(&s_mb[wid][1]);
    const uint32_t sbA = smem_u32(&sbuf[wid][0][0]);
    const uint32_t sbB = smem_u32(&sbuf[wid][1][0]);

    if (lane == 0) { mbar_init(mbA, 1); mbar_init(mbB, 1); }
    __syncthreads();   // one-time: all mbarriers visible before any TMA

    float4 cs[8];
    const float4* csrow = (const float4*)g_cs[c];
#pragma unroll
    for (int k = 0; k < 8; k++) cs[k] = csrow[2 * k + h];
    const float bias = g_bias[c];

    float2 acc[16];                 // lane = dim-pair: class i, dims 2lane..+1
#pragma unroll
    for (int i = 0; i < 16; i++) { acc[i].x = 0.f; acc[i].y = 0.f; }
    float ws = 0.f;                 // lanes<16: sum of w for class==lane

    int mt = blockIdx.x * NWARPS + wid;
    if (lane == 0 && mt < NMT) {
        mbar_expect(mbA, WBYTES);
        bulk_g2s(sbA, qf + (size_t)mt * WTD, WBYTES, mbA);
    }
    int buf = 0;
    uint32_t phA = 0, phB = 0;

    for (; mt < NMT; mt += MSTRIDE) {
        int tn = mt + MSTRIDE;
        if (lane == 0 && tn < NMT) {
            mbar_expect(buf ? mbA : mbB, WBYTES);
            bulk_g2s(buf ? sbA : sbB, qf + (size_t)tn * WTD, WBYTES,
                     buf ? mbA : mbB);
        }
        if (buf == 0) { mbar_wait(mbA, phA); phA ^= 1; }
        else          { mbar_wait(mbB, phB); phB ^= 1; }

        const float* base = &sbuf[wid][buf][0];

        // ---- pA: 8 dots -> logits (8-wide ILP) ----
        float logit[QPW];
#pragma unroll
        for (int qi = 0; qi < QPW; qi++) {
            const float4* qrow = (const float4*)(base + qi * DIM);
            float2 dA = {0.f, 0.f}, dB = {0.f, 0.f};
#pragma unroll
            for (int k = 0; k < 8; k++) {
                float4 qv = qrow[2 * k + h];
                float2 q01 = {qv.x, qv.y}, q23 = {qv.z, qv.w};
                float2 c01 = {cs[k].x, cs[k].y}, c23 = {cs[k].z, cs[k].w};
                dA = ffma2(q01, c01, dA);
                dB = ffma2(q23, c23, dB);
            }
            float dot = (dA.x + dA.y) + (dB.x + dB.y);
            dot += __shfl_xor_sync(0xffffffffu, dot, 16);
            logit[qi] = dot - bias;
        }

        // ---- max over classes (interleaved butterflies) ----
        float mx[QPW];
#pragma unroll
        for (int qi = 0; qi < QPW; qi++) mx[qi] = logit[qi];
#pragma unroll
        for (int msk = 8; msk >= 1; msk >>= 1) {
#pragma unroll
            for (int qi = 0; qi < QPW; qi++)
                mx[qi] = fmaxf(mx[qi], __shfl_xor_sync(0xffffffffu, mx[qi], msk));
        }

        // ---- exp, stash e per class into per-warp smem ----
        float e_reg[QPW];
#pragma unroll
        for (int qi = 0; qi < QPW; qi++)
            e_reg[qi] = __expf(logit[qi] - mx[qi]);
        if (lane < 16) {
#pragma unroll
            for (int qi = 0; qi < QPW; qi++) sE[wid][qi][lane] = e_reg[qi];
        }
        __syncwarp();

        // ---- pB: transposed accumulate, FFMA2-packed ----
        const float* eb = &sE[wid][0][0];
#pragma unroll 4
        for (int qi = 0; qi < QPW; qi++) {
            float2 q2 = *(const float2*)(base + qi * DIM + 2 * lane);
            const float4* er = (const float4*)(eb + qi * 16);
            float4 r0 = er[0], r1 = er[1], r2 = er[2], r3 = er[3];

            float2 s1 = fadd2({r0.x, r0.y}, {r1.x, r1.y});
            float2 s2 = fadd2({r0.z, r0.w}, {r1.z, r1.w});
            float2 s3 = fadd2({r2.x, r2.y}, {r3.x, r3.y});
            float2 s4 = fadd2({r2.z, r2.w}, {r3.z, r3.w});
            float2 s5 = fadd2(s1, s2);
            float2 s6 = fadd2(s3, s4);
            float2 s7 = fadd2(s5, s6);
            float inv = frcp(s7.x + s7.y);

            float2 qs = {q2.x * inv, q2.y * inv};
            float ev[16] = {r0.x, r0.y, r0.z, r0.w, r1.x, r1.y, r1.z, r1.w,
                            r2.x, r2.y, r2.z, r2.w, r3.x, r3.y, r3.z, r3.w};
#pragma unroll
            for (int i = 0; i < 16; i++)
                acc[i] = ffma2({ev[i], ev[i]}, qs, acc[i]);
            if (lane < 16) ws = fmaf(e_reg[qi], inv, ws);
        }

        buf ^= 1;
        __syncwarp();   // warp-local: reads of this buffer + sE done
    }

    // ---- deterministic serialized flush into [16][64] partials ----
    __syncthreads();
    for (int r = 0; r < NWARPS; r++) {
        if (wid == r) {
            if (r == 0) {
#pragma unroll
                for (int i = 0; i < 16; i++) {
                    facc[i][2 * lane]     = acc[i].x;
                    facc[i][2 * lane + 1] = acc[i].y;
                }
                sws[lane] = ws;
            } else {
#pragma unroll
                for (int i = 0; i < 16; i++) {
                    facc[i][2 * lane]     += acc[i].x;
                    facc[i][2 * lane + 1] += acc[i].y;
                }
                sws[lane] += ws;
            }
        }
        __syncthreads();
    }
    {
        const float4* fs = (const float4*)&facc[0][0];
        ((float4*)&g_part[blockIdx.x][0][0])[tid] = fs[tid];
        if (tid < NCLS) g_pden[blockIdx.x][tid] = sws[tid];
    }
}

// ---------------- centroid update (16 blocks) -------------------------------
__global__ void reduce_kernel() {
    __shared__ float red[4][DIM];
    __shared__ float dch[4];
    __shared__ float sqv[DIM];
    __shared__ float den_s;

    const int c  = blockIdx.x;
    const int tid = threadIdx.x;          // 256
    const int d  = tid & 63;
    const int ch = tid >> 6;              // 0..3
    const int per = GRID_MAIN / 4;        // 74

    float s = 0.f, ds = 0.f;
    const int b0 = ch * per;
    for (int b = b0; b < b0 + per; b++) {
        s += g_part[b][c][d];
        if (d == 0) ds += g_pden[b][c];
    }
    red[ch][d] = s;
    if (d == 0) dch[ch] = ds;
    __syncthreads();

    if (tid == 0)
        den_s = g_counts[c] + dch[0] + dch[1] + dch[2] + dch[3];
    __syncthreads();

    if (tid < DIM) {
        float tot = red[0][tid] + red[1][tid] + red[2][tid] + red[3][tid];
        float num = g_sup_sum[c][tid] + tot;
        float cd  = num / den_s;
        g_cs[c][tid] = 2.0f * BETA_F * cd;
        sqv[tid] = cd * cd;
    }
    __syncthreads();
    if (tid == 0) {
        float sq = 0.f;
#pragma unroll
        for (int k = 0; k < DIM; k++) sq += sqv[k];
        g_bias[c] = BETA_F * sq;
    }
}

// ---------------- final prediction (R9, unchanged) --------------------------
__global__ void __launch_bounds__(TPB, 2)
predict_kernel(const float* __restrict__ qf, const void* __restrict__ qlab) {
    __shared__ alignas(128) float sbuf[2][TQD];
    __shared__ alignas(8) unsigned long long s_mb[2];
    __shared__ int scnt[NWARPS];

    const int tid  = threadIdx.x;
    const int wid  = tid >> 5;
    const int lane = tid & 31;
    const int c    = lane & 15;
    const int h    = lane >> 4;

    const uint32_t mb0 = smem_u32(&s_mb[0]);
    const uint32_t mb1 = smem_u32(&s_mb[1]);
    const uint32_t sb0 = smem_u32(&sbuf[0][0]);
    const uint32_t sb1 = smem_u32(&sbuf[1][0]);

    if (tid == 0) { mbar_init(mb0, 1); mbar_init(mb1, 1); }
    __syncthreads();

    float4 cs[8];
    const float4* csrow = (const float4*)g_cs[c];
#pragma unroll
    for (int k = 0; k < 8; k++) cs[k] = csrow[2 * k + h];
    const float bias = g_bias[c];

    const int is64 = g_lab64;
    const long long* L64 = (const long long*)qlab;
    const int*       L32 = (const int*)qlab;

    int cnt = 0;
    int t = blockIdx.x;
    if (tid == 0 && t < NTILES) {
        mbar_expect(mb0, TBYTES);
        bulk_g2s(sb0, qf + (size_t)t * TQD, TBYTES, mb0);
    }
    int buf = 0;
    uint32_t ph0 = 0, ph1 = 0;

    for (; t < NTILES; t += gridDim.x) {
        int tn = t + gridDim.x;
        if (tid == 0 && tn < NTILES) {
            uint32_t mbn = buf ? mb0 : mb1;
            mbar_expect(mbn, TBYTES);
            bulk_g2s(buf ? sb0 : sb1, qf + (size_t)tn * TQD, TBYTES, mbn);
        }
        if (buf == 0) { mbar_wait(mb0, ph0); ph0 ^= 1; }
        else          { mbar_wait(mb1, ph1); ph1 ^= 1; }

        const float* base = sbuf[buf] + wid * 8 * DIM;

        float v[8];
#pragma unroll
        for (int qi = 0; qi < 8; qi++) {
            const float4* qrow = (const float4*)(base + qi * DIM);
            float2 dA = {0.f, 0.f}, dB = {0.f, 0.f};
#pragma unroll
            for (int k = 0; k < 8; k++) {
                float4 qv = qrow[2 * k + h];
                float2 q01 = {qv.x, qv.y}, q23 = {qv.z, qv.w};
                float2 c01 = {cs[k].x, cs[k].y}, c23 = {cs[k].z, cs[k].w};
                dA = ffma2(q01, c01, dA);
                dB = ffma2(q23, c23, dB);
            }
            float dot = (dA.x + dA.y) + (dB.x + dB.y);
            dot += __shfl_xor_sync(0xffffffffu, dot, 16);
            v[qi] = dot - bias;
        }

        int bi[8];
#pragma unroll
        for (int qi = 0; qi < 8; qi++) bi[qi] = c;
#pragma unroll
        for (int msk = 8; msk >= 1; msk >>= 1) {
#pragma unroll
            for (int qi = 0; qi < 8; qi++) {
                float ov = __shfl_xor_sync(0xffffffffu, v[qi], msk);
                int   oi = __shfl_xor_sync(0xffffffffu, bi[qi], msk);
                if (ov > v[qi] || (ov == v[qi] && oi < bi[qi])) {
                    v[qi] = ov; bi[qi] = oi;
                }
            }
        }
        if (lane == 0) {
#pragma unroll
            for (int qi = 0; qi < 8; qi++) {
                int qg = t * TILE_Q + wid * 8 + qi;
                int lbl = is64 ? (int)L64[qg] : L32[qg];
                if (bi[qi] == lbl) cnt++;
            }
        }
        buf ^= 1;
        __syncthreads();
    }

    if (lane == 0) scnt[wid] = cnt;
    __syncthreads();
    if (tid == 0) {
        int bc = 0;
#pragma unroll
        for (int w = 0; w < NWARPS; w++) bc += scnt[w];
        atomicAdd(&g_match, bc);
    }
}

__global__ void finalize_kernel(float* out) {
    out[0] = (float)g_match / (float)NQ;
}

// ---------------- launch ----------------------------------------------------
extern "C" void kernel_launch(void* const* d_in, const int* in_sizes, int n_in,
                              void* d_out, int out_size) {
    (void)in_sizes; (void)n_in; (void)out_size;
    const float* sup  = (const float*)d_in[0];
    const float* qf   = (const float*)d_in[1];
    const void*  slab = d_in[2];
    const void*  qlab = d_in[3];
    float* out = (float*)d_out;

    init_kernel<<<1, 512>>>(sup, slab);
    for (int it = 0; it < NITER; ++it) {
        iter_kernel<<<GRID_MAIN, TPB>>>(qf);
        reduce_kernel<<<NCLS, 256>>>();
    }
    predict_kernel<<<GRID_MAIN, TPB>>>(qf, qlab);
    finalize_kernel<<<1, 1>>>(out);
}

// round 17
// speedup vs baseline: 1.2352x; 1.0133x over previous
#include <cuda_runtime.h>
#include <cstdint>

// ============================================================================
// Soft K-means — R16: R15 per-warp streams, but staging via per-warp cp.async
// commit/wait groups instead of TMA+mbarrier (TRYWAIT ~60-90cyc/tile was the
// largest identified issue hole at 8-query tile granularity).
// ============================================================================

#define NQ        (1 << 21)
#define DIM       64
#define NCLS      16
#define NSUP      512
#define NITER     50
#define BETA_F    5.0f
#define GRID_MAIN 296
#define TPB       256
#define NWARPS    (TPB / 32)
#define QPW       8                     // queries per warp-tile
#define WTD       (QPW * DIM)           // 512 floats = 2KB
#define NMT       (NQ / QPW)            // 262144 mini-tiles
#define MSTRIDE   (GRID_MAIN * NWARPS)  // 2368 warp streams
// predict kernel geometry (block tiles, unchanged)
#define TILE_Q    64
#define NTILES    (NQ / TILE_Q)
#define TQD       (TILE_Q * DIM)
#define TBYTES    (TQD * 4)

__device__ float  g_sup_sum[NCLS][DIM];
__device__ float  g_counts[NCLS];
__device__ float  g_cs[NCLS][DIM];                 // 2*beta*centroid
__device__ float  g_bias[NCLS];                    // beta*|centroid|^2
__device__ float  g_part[GRID_MAIN][NCLS][DIM];    // per-block partials
__device__ float  g_pden[GRID_MAIN][NCLS];
__device__ int    g_match;
__device__ int    g_lab64;

// ---------------- helpers ---------------------------------------------------
__device__ __forceinline__ float2 ffma2(const float2 a, const float2 b,
                                        const float2 c) {
    float2 r;
    asm("{.reg .b64 ra,rb,rc;\n\t"
        "mov.b64 ra,{%2,%3};\n\tmov.b64 rb,{%4,%5};\n\tmov.b64 rc,{%6,%7};\n\t"
        "fma.rn.f32x2 rc, ra, rb, rc;\n\tmov.b64 {%0,%1}, rc;}\n"
        : "=f"(r.x), "=f"(r.y)
        : "f"(a.x), "f"(a.y), "f"(b.x), "f"(b.y), "f"(c.x), "f"(c.y));
    return r;
}
__device__ __forceinline__ float2 fadd2(const float2 a, const float2 b) {
    float2 r;
    asm("{.reg .b64 ra,rb;\n\t"
        "mov.b64 ra,{%2,%3};\n\tmov.b64 rb,{%4,%5};\n\t"
        "add.rn.f32x2 ra, ra, rb;\n\tmov.b64 {%0,%1}, ra;}\n"
        : "=f"(r.x), "=f"(r.y)
        : "f"(a.x), "f"(a.y), "f"(b.x), "f"(b.y));
    return r;
}
__device__ __forceinline__ float frcp(float x) {
    float r;
    asm("rcp.approx.f32 %0, %1;" : "=f"(r) : "f"(x));
    return r;
}
__device__ __forceinline__ uint32_t smem_u32(const void* p) {
    uint32_t a;
    asm("{ .reg .u64 t; cvta.to.shared.u64 t, %1; cvt.u32.u64 %0, t; }"
        : "=r"(a) : "l"(p));
    return a;
}
__device__ __forceinline__ void cp16(void* smem_dst, const void* gsrc) {
    unsigned s = (unsigned)__cvta_generic_to_shared(smem_dst);
    asm volatile("cp.async.cg.shared.global [%0], [%1], 16;\n"
                 :: "r"(s), "l"(gsrc));
}
#define CP_COMMIT() asm volatile("cp.async.commit_group;\n" ::: "memory")
#define CP_WAIT1()  asm volatile("cp.async.wait_group 1;\n" ::: "memory")
// block-level staging for predict_kernel
__device__ __forceinline__ void mbar_init(uint32_t a, uint32_t n) {
    asm volatile("mbarrier.init.shared.b64 [%0], %1;" :: "r"(a), "r"(n)
                 : "memory");
}
__device__ __forceinline__ void mbar_expect(uint32_t a, uint32_t bytes) {
    asm volatile("mbarrier.arrive.expect_tx.shared.b64 _, [%0], %1;"
                 :: "r"(a), "r"(bytes) : "memory");
}
__device__ __forceinline__ void bulk_g2s(uint32_t dst, const void* src,
                                         uint32_t bytes, uint32_t mbar) {
    asm volatile(
        "cp.async.bulk.shared::cluster.global.mbarrier::complete_tx::bytes "
        "[%0], [%1], %2, [%3];"
        :: "r"(dst), "l"(src), "r"(bytes), "r"(mbar) : "memory");
}
__device__ __forceinline__ void mbar_wait(uint32_t a, uint32_t par) {
    uint32_t done;
    asm volatile(
        "{\n\t.reg .pred p;\n\t"
        "mbarrier.try_wait.parity.acquire.cta.shared::cta.b64 p, [%1], %2;\n\t"
        "selp.b32 %0, 1, 0, p;\n\t}"
        : "=r"(done) : "r"(a), "r"(par) : "memory");
    if (!done) {
        asm volatile(
            "{\n\t.reg .pred P1;\n\t"
            "W_%=:\n\t"
            "mbarrier.try_wait.parity.acquire.cta.shared::cta.b64 P1, [%0], %1, 0x989680;\n\t"
            "@P1 bra.uni D_%=;\n\tbra.uni W_%=;\n\tD_%=:\n\t}"
            :: "r"(a), "r"(par) : "memory");
    }
}

// ---------------- init ------------------------------------------------------
__global__ void init_kernel(const float* __restrict__ sup, const void* slab) {
    __shared__ int s64;
    if (threadIdx.x == 0) {
        const unsigned long long* p = (const unsigned long long*)slab;
        int is64 = 1;
#pragma unroll
        for (int i = 0; i < 4; i++)
            if ((p[i] >> 32) != 0ull) is64 = 0;
        s64 = is64;
        g_lab64 = is64;
        g_match = 0;
    }
    __syncthreads();
    const int is64 = s64;
    const int c = threadIdx.x >> 5;
    const int j = threadIdx.x & 31;
    const long long* l64 = (const long long*)slab;
    const int*       l32 = (const int*)slab;

    float sx = 0.f, sy = 0.f;
    int cnt = 0;
    for (int s = 0; s < NSUP; s++) {
        int lbl = is64 ? (int)l64[s] : l32[s];
        if (lbl == c) {
            float2 v = ((const float2*)(sup + s * DIM))[j];
            sx += v.x; sy += v.y; cnt++;
        }
    }
    g_sup_sum[c][2 * j]     = sx;
    g_sup_sum[c][2 * j + 1] = sy;
    float inv = 1.0f / (float)cnt;
    float c0 = sx * inv, c1 = sy * inv;
    g_cs[c][2 * j]     = 2.0f * BETA_F * c0;
    g_cs[c][2 * j + 1] = 2.0f * BETA_F * c1;
    float sq = c0 * c0 + c1 * c1;
#pragma unroll
    for (int m = 16; m > 0; m >>= 1)
        sq += __shfl_xor_sync(0xffffffffu, sq, m);
    if (j == 0) {
        g_counts[c] = (float)cnt;
        g_bias[c]   = BETA_F * sq;
    }
}

// ---------------- fused iteration kernel (per-warp cp.async streams) --------
__global__ void __launch_bounds__(TPB, 2)
iter_kernel(const float* __restrict__ qf) {
    __shared__ alignas(128) float sbuf[NWARPS][2][WTD];  // 32 KB
    __shared__ alignas(16) float sE[NWARPS][QPW][16];    // 4 KB
    __shared__ float facc[NCLS][DIM];                    // 4 KB
    __shared__ float sws[32];

    const int tid  = threadIdx.x;
    const int wid  = tid >> 5;
    const int lane = tid & 31;
    const int c    = lane & 15;
    const int h    = lane >> 4;

    float4 cs[8];
    const float4* csrow = (const float4*)g_cs[c];
#pragma unroll
    for (int k = 0; k < 8; k++) cs[k] = csrow[2 * k + h];
    const float bias = g_bias[c];

    float2 acc[16];                 // lane = dim-pair: class i, dims 2lane..+1
#pragma unroll
    for (int i = 0; i < 16; i++) { acc[i].x = 0.f; acc[i].y = 0.f; }
    float ws = 0.f;                 // lanes<16: sum of w for class==lane

    int mt = blockIdx.x * NWARPS + wid;
    if (mt < NMT) {
        const float4* s4 = (const float4*)(qf + (size_t)mt * WTD);
        float4* d4 = (float4*)&sbuf[wid][0][0];
#pragma unroll
        for (int k = 0; k < 4; k++)
            cp16(&d4[k * 32 + lane], &s4[k * 32 + lane]);
    }
    CP_COMMIT();
    int buf = 0;

    for (; mt < NMT; mt += MSTRIDE) {
        int tn = mt + MSTRIDE;
        if (tn < NMT) {
            const float4* s4 = (const float4*)(qf + (size_t)tn * WTD);
            float4* d4 = (float4*)&sbuf[wid][buf ^ 1][0];
#pragma unroll
            for (int k = 0; k < 4; k++)
                cp16(&d4[k * 32 + lane], &s4[k * 32 + lane]);
        }
        CP_COMMIT();
        CP_WAIT1();
        __syncwarp();

        const float* base = &sbuf[wid][buf][0];

        // ---- pA: 8 dots -> logits (8-wide ILP) ----
        float logit[QPW];
#pragma unroll
        for (int qi = 0; qi < QPW; qi++) {
            const float4* qrow = (const float4*)(base + qi * DIM);
            float2 dA = {0.f, 0.f}, dB = {0.f, 0.f};
#pragma unroll
            for (int k = 0; k < 8; k++) {
                float4 qv = qrow[2 * k + h];
                float2 q01 = {qv.x, qv.y}, q23 = {qv.z, qv.w};
                float2 c01 = {cs[k].x, cs[k].y}, c23 = {cs[k].z, cs[k].w};
                dA = ffma2(q01, c01, dA);
                dB = ffma2(q23, c23, dB);
            }
            float dot = (dA.x + dA.y) + (dB.x + dB.y);
            dot += __shfl_xor_sync(0xffffffffu, dot, 16);
            logit[qi] = dot - bias;
        }

        // ---- max over classes (interleaved butterflies) ----
        float mx[QPW];
#pragma unroll
        for (int qi = 0; qi < QPW; qi++) mx[qi] = logit[qi];
#pragma unroll
        for (int msk = 8; msk >= 1; msk >>= 1) {
#pragma unroll
            for (int qi = 0; qi < QPW; qi++)
                mx[qi] = fmaxf(mx[qi], __shfl_xor_sync(0xffffffffu, mx[qi], msk));
        }

        // ---- exp, stash e per class into per-warp smem ----
        float e_reg[QPW];
#pragma unroll
        for (int qi = 0; qi < QPW; qi++)
            e_reg[qi] = __expf(logit[qi] - mx[qi]);
        if (lane < 16) {
#pragma unroll
            for (int qi = 0; qi < QPW; qi++) sE[wid][qi][lane] = e_reg[qi];
        }
        __syncwarp();

        // ---- pB: transposed accumulate, FFMA2-packed ----
        const float* eb = &sE[wid][0][0];
#pragma unroll 4
        for (int qi = 0; qi < QPW; qi++) {
            float2 q2 = *(const float2*)(base + qi * DIM + 2 * lane);
            const float4* er = (const float4*)(eb + qi * 16);
            float4 r0 = er[0], r1 = er[1], r2 = er[2], r3 = er[3];

            float2 s1 = fadd2({r0.x, r0.y}, {r1.x, r1.y});
            float2 s2 = fadd2({r0.z, r0.w}, {r1.z, r1.w});
            float2 s3 = fadd2({r2.x, r2.y}, {r3.x, r3.y});
            float2 s4 = fadd2({r2.z, r2.w}, {r3.z, r3.w});
            float2 s5 = fadd2(s1, s2);
            float2 s6 = fadd2(s3, s4);
            float2 s7 = fadd2(s5, s6);
            float inv = frcp(s7.x + s7.y);

            float2 qs = {q2.x * inv, q2.y * inv};
            float ev[16] = {r0.x, r0.y, r0.z, r0.w, r1.x, r1.y, r1.z, r1.w,
                            r2.x, r2.y, r2.z, r2.w, r3.x, r3.y, r3.z, r3.w};
#pragma unroll
            for (int i = 0; i < 16; i++)
                acc[i] = ffma2({ev[i], ev[i]}, qs, acc[i]);
            if (lane < 16) ws = fmaf(e_reg[qi], inv, ws);
        }

        buf ^= 1;
        __syncwarp();   // warp-local: reads of this buffer + sE done
    }

    // ---- deterministic serialized flush into [16][64] partials ----
    __syncthreads();
    for (int r = 0; r < NWARPS; r++) {
        if (wid == r) {
            if (r == 0) {
#pragma unroll
                for (int i = 0; i < 16; i++) {
                    facc[i][2 * lane]     = acc[i].x;
                    facc[i][2 * lane + 1] = acc[i].y;
                }
                sws[lane] = ws;
            } else {
#pragma unroll
                for (int i = 0; i < 16; i++) {
                    facc[i][2 * lane]     += acc[i].x;
                    facc[i][2 * lane + 1] += acc[i].y;
                }
                sws[lane] += ws;
            }
        }
        __syncthreads();
    }
    {
        const float4* fs = (const float4*)&facc[0][0];
        ((float4*)&g_part[blockIdx.x][0][0])[tid] = fs[tid];
        if (tid < NCLS) g_pden[blockIdx.x][tid] = sws[tid];
    }
}

// ---------------- centroid update (16 blocks) -------------------------------
__global__ void reduce_kernel() {
    __shared__ float red[4][DIM];
    __shared__ float dch[4];
    __shared__ float sqv[DIM];
    __shared__ float den_s;

    const int c  = blockIdx.x;
    const int tid = threadIdx.x;          // 256
    const int d  = tid & 63;
    const int ch = tid >> 6;              // 0..3
    const int per = GRID_MAIN / 4;        // 74

    float s = 0.f, ds = 0.f;
    const int b0 = ch * per;
    for (int b = b0; b < b0 + per; b++) {
        s += g_part[b][c][d];
        if (d == 0) ds += g_pden[b][c];
    }
    red[ch][d] = s;
    if (d == 0) dch[ch] = ds;
    __syncthreads();

    if (tid == 0)
        den_s = g_counts[c] + dch[0] + dch[1] + dch[2] + dch[3];
    __syncthreads();

    if (tid < DIM) {
        float tot = red[0][tid] + red[1][tid] + red[2][tid] + red[3][tid];
        float num = g_sup_sum[c][tid] + tot;
        float cd  = num / den_s;
        g_cs[c][tid] = 2.0f * BETA_F * cd;
        sqv[tid] = cd * cd;
    }
    __syncthreads();
    if (tid == 0) {
        float sq = 0.f;
#pragma unroll
        for (int k = 0; k < DIM; k++) sq += sqv[k];
        g_bias[c] = BETA_F * sq;
    }
}

// ---------------- final prediction (unchanged) ------------------------------
__global__ void __launch_bounds__(TPB, 2)
predict_kernel(const float* __restrict__ qf, const void* __restrict__ qlab) {
    __shared__ alignas(128) float sbuf[2][TQD];
    __shared__ alignas(8) unsigned long long s_mb[2];
    __shared__ int scnt[NWARPS];

    const int tid  = threadIdx.x;
    const int wid  = tid >> 5;
    const int lane = tid & 31;
    const int c    = lane & 15;
    const int h    = lane >> 4;

    const uint32_t mb0 = smem_u32(&s_mb[0]);
    const uint32_t mb1 = smem_u32(&s_mb[1]);
    const uint32_t sb0 = smem_u32(&sbuf[0][0]);
    const uint32_t sb1 = smem_u32(&sbuf[1][0]);

    if (tid == 0) { mbar_init(mb0, 1); mbar_init(mb1, 1); }
    __syncthreads();

    float4 cs[8];
    const float4* csrow = (const float4*)g_cs[c];
#pragma unroll
    for (int k = 0; k < 8; k++) cs[k] = csrow[2 * k + h];
    const float bias = g_bias[c];

    const int is64 = g_lab64;
    const long long* L64 = (const long long*)qlab;
    const int*       L32 = (const int*)qlab;

    int cnt = 0;
    int t = blockIdx.x;
    if (tid == 0 && t < NTILES) {
        mbar_expect(mb0, TBYTES);
        bulk_g2s(sb0, qf + (size_t)t * TQD, TBYTES, mb0);
    }
    int buf = 0;
    uint32_t ph0 = 0, ph1 = 0;

    for (; t < NTILES; t += gridDim.x) {
        int tn = t + gridDim.x;
        if (tid == 0 && tn < NTILES) {
            uint32_t mbn = buf ? mb0 : mb1;
            mbar_expect(mbn, TBYTES);
            bulk_g2s(buf ? sb0 : sb1, qf + (size_t)tn * TQD, TBYTES, mbn);
        }
        if (buf == 0) { mbar_wait(mb0, ph0); ph0 ^= 1; }
        else          { mbar_wait(mb1, ph1); ph1 ^= 1; }

        const float* base = sbuf[buf] + wid * 8 * DIM;

        float v[8];
#pragma unroll
        for (int qi = 0; qi < 8; qi++) {
            const float4* qrow = (const float4*)(base + qi * DIM);
            float2 dA = {0.f, 0.f}, dB = {0.f, 0.f};
#pragma unroll
            for (int k = 0; k < 8; k++) {
                float4 qv = qrow[2 * k + h];
                float2 q01 = {qv.x, qv.y}, q23 = {qv.z, qv.w};
                float2 c01 = {cs[k].x, cs[k].y}, c23 = {cs[k].z, cs[k].w};
                dA = ffma2(q01, c01, dA);
                dB = ffma2(q23, c23, dB);
            }
            float dot = (dA.x + dA.y) + (dB.x + dB.y);
            dot += __shfl_xor_sync(0xffffffffu, dot, 16);
            v[qi] = dot - bias;
        }

        int bi[8];
#pragma unroll
        for (int qi = 0; qi < 8; qi++) bi[qi] = c;
#pragma unroll
        for (int msk = 8; msk >= 1; msk >>= 1) {
#pragma unroll
            for (int qi = 0; qi < 8; qi++) {
                float ov = __shfl_xor_sync(0xffffffffu, v[qi], msk);
                int   oi = __shfl_xor_sync(0xffffffffu, bi[qi], msk);
                if (ov > v[qi] || (ov == v[qi] && oi < bi[qi])) {
                    v[qi] = ov; bi[qi] = oi;
                }
            }
        }
        if (lane == 0) {
#pragma unroll
            for (int qi = 0; qi < 8; qi++) {
                int qg = t * TILE_Q + wid * 8 + qi;
                int lbl = is64 ? (int)L64[qg] : L32[qg];
                if (bi[qi] == lbl) cnt++;
            }
        }
        buf ^= 1;
        __syncthreads();
    }

    if (lane == 0) scnt[wid] = cnt;
    __syncthreads();
    if (tid == 0) {
        int bc = 0;
#pragma unroll
        for (int w = 0; w < NWARPS; w++) bc += scnt[w];
        atomicAdd(&g_match, bc);
    }
}

__global__ void finalize_kernel(float* out) {
    out[0] = (float)g_match / (float)NQ;
}

// ---------------- launch ----------------------------------------------------
extern "C" void kernel_launch(void* const* d_in, const int* in_sizes, int n_in,
                              void* d_out, int out_size) {
    (void)in_sizes; (void)n_in; (void)out_size;
    const float* sup  = (const float*)d_in[0];
    const float* qf   = (const float*)d_in[1];
    const void*  slab = d_in[2];
    const void*  qlab = d_in[3];
    float* out = (float*)d_out;

    init_kernel<<<1, 512>>>(sup, slab);
    for (int it = 0; it < NITER; ++it) {
        iter_kernel<<<GRID_MAIN, TPB>>>(qf);
        reduce_kernel<<<NCLS, 256>>>();
    }
    predict_kernel<<<GRID_MAIN, TPB>>>(qf, qlab);
    finalize_kernel<<<1, 1>>>(out);
}